// round 15
// baseline (speedup 1.0000x reference)
#include <cuda_runtime.h>
#include <cuda_bf16.h>
#include <cstdint>

#define N_NODES 100000
#define N_EDGES 1600000
#define D       128
#define N_LAYERS 4
#define N_GRAPHS 64
#define N_CLASS 10

// ---------------- scratch (device globals: no allocation allowed) ----------
__device__ float g_b[N_NODES * D];     // per-layer MLP output (pre-BN)
__device__ float g_c[N_NODES * D];     // aggregate output (MLP input)
__device__ int   g_deg[N_NODES];
__device__ int   g_rowptr[N_NODES + 1];
__device__ int   g_cursor[N_NODES];
__device__ int   g_eidx[N_EDGES];
__device__ int   g_bsum[512];
__device__ int   g_bsumx[512];
__device__ float g_xacc[2 * D];
__device__ float g_bnacc[N_LAYERS * 2 * D];   // per-layer sum/sumsq
__device__ float g_sc0[D], g_sh0[D];          // standardization affine
__device__ float g_pool[N_GRAPHS * D];
__device__ float g_fc1o[N_GRAPHS * D];
__device__ float g_fc2o[N_GRAPHS * (D / 2)];
// pre-split weights in per-lane mma fragment order:
// [mat][ (kstep*16 + ntile)*32 + lane ] = {bhi0, bhi1, blo0, blo1}
__device__ uint4 g_wfrag[8 * 4096];

#define SCAN_B 391
#define GB_GEMM 782                    // ceil(100000/128), 128 rows per CTA
#define NT 16                          // n-tiles of 8 cols -> 128 cols
#define MLP_SMEM (8192 * 16)           // 128 KB: W1 + W2 fragment tables

// ---------------- mma helpers ------------------------------------------------
__device__ __forceinline__ uint32_t b2u(__nv_bfloat162 h) {
    return reinterpret_cast<uint32_t&>(h);
}
__device__ __forceinline__ void split2(float2 v, uint32_t& hi, uint32_t& lo) {
    __nv_bfloat162 h = __float22bfloat162_rn(v);
    float2 hf = __bfloat1622float2(h);
    __nv_bfloat162 l = __float22bfloat162_rn(make_float2(v.x - hf.x, v.y - hf.y));
    hi = b2u(h);
    lo = b2u(l);
}
__device__ __forceinline__ void mma_bf16(float c[4],
                                         uint32_t a0, uint32_t a1, uint32_t a2, uint32_t a3,
                                         uint32_t b0, uint32_t b1) {
    asm volatile(
        "mma.sync.aligned.m16n8k16.row.col.f32.bf16.bf16.f32 "
        "{%0,%1,%2,%3}, {%4,%5,%6,%7}, {%8,%9}, {%0,%1,%2,%3};"
        : "+f"(c[0]), "+f"(c[1]), "+f"(c[2]), "+f"(c[3])
        : "r"(a0), "r"(a1), "r"(a2), "r"(a3), "r"(b0), "r"(b1));
}

// ---------------- weight prep: transpose + split + fragment pack ------------
__global__ void k_wprep(const float* __restrict__ W1, const float* __restrict__ W2) {
    int mat = blockIdx.x;                    // 0..7 = layer*2 + which
    int layer = mat >> 1;
    const float* src = ((mat & 1) ? W2 : W1) + layer * D * D;   // src[k*D + n]
    uint4* dst = g_wfrag + mat * 4096;
    for (int i = threadIdx.x; i < 4096; i += blockDim.x) {
        int l = i & 31;
        int pair = i >> 5;                   // 0..127
        int s = pair >> 4, nt = pair & 15;   // kstep, ntile
        int g = l >> 2, t = l & 3;
        int n = nt * 8 + g;
        int k0 = s * 16 + t * 2;
        float2 w0 = make_float2(src[k0 * D + n],       src[(k0 + 1) * D + n]);
        float2 w1 = make_float2(src[(k0 + 8) * D + n], src[(k0 + 9) * D + n]);
        uint32_t h0, l0, h1, l1;
        split2(w0, h0, l0);
        split2(w1, h1, l1);
        dst[i] = make_uint4(h0, h1, l0, l1);
    }
}

// ---------------- fused MLP: out = relu(relu(A@W1+b1)@W2+b2), + BN stats ----
// Z1 never leaves registers: GEMM1's C-fragment layout == GEMM2's A-fragment
// layout (lane (g,t) holds rows r0/r1 at col pairs {8*nt+2t, +1}; k-step s of
// GEMM2 consumes exactly nt=2s and nt=2s+1).
__global__ void __launch_bounds__(256, 1)
k_mlp(const float* __restrict__ A,
      const uint4* __restrict__ Wf1, const uint4* __restrict__ Wf2,
      const float* __restrict__ bias1, const float* __restrict__ bias2,
      float* __restrict__ out, int M, float* __restrict__ bnacc) {
    extern __shared__ uint4 sfrag[];       // [0..4095]=W1, [4096..8191]=W2
    __shared__ float sbias1[128], sbias2[128];
    __shared__ float sred[2][8][128];      // BN partials per warp

    const int tid = threadIdx.x;
    const int w = tid >> 5, l = tid & 31;
    const int g = l >> 2, t = l & 3;

    for (int i = tid; i < 4096; i += 256) sfrag[i] = Wf1[i];
    for (int i = tid; i < 4096; i += 256) sfrag[4096 + i] = Wf2[i];
    if (tid < 128) { sbias1[tid] = bias1[tid]; sbias2[tid] = bias2[tid]; }
    __syncthreads();

    const int m0 = blockIdx.x * 128;
    const int row0 = m0 + w * 16 + g;
    const int row1 = row0 + 8;
    const float* p0 = A + (size_t)min(row0, M - 1) * 128 + 2 * t;
    const float* p1 = A + (size_t)min(row1, M - 1) * 128 + 2 * t;

    float acc[NT][4];
#pragma unroll
    for (int nt = 0; nt < NT; ++nt) {
        acc[nt][0] = 0.f; acc[nt][1] = 0.f; acc[nt][2] = 0.f; acc[nt][3] = 0.f;
    }

    // ---- GEMM1: acc = A @ W1 (split-bf16, 3 terms) ----
    {
        float2 f0 = *(const float2*)p0;
        float2 f1 = *(const float2*)p1;
        float2 f2 = *(const float2*)(p0 + 8);
        float2 f3 = *(const float2*)(p1 + 8);
#pragma unroll
        for (int s = 0; s < 8; ++s) {
            float2 n0, n1, n2, n3;
            if (s < 7) {
                n0 = *(const float2*)(p0 + (s + 1) * 16);
                n1 = *(const float2*)(p1 + (s + 1) * 16);
                n2 = *(const float2*)(p0 + (s + 1) * 16 + 8);
                n3 = *(const float2*)(p1 + (s + 1) * 16 + 8);
            }
            uint32_t ah0, al0, ah1, al1, ah2, al2, ah3, al3;
            split2(f0, ah0, al0);
            split2(f1, ah1, al1);
            split2(f2, ah2, al2);
            split2(f3, ah3, al3);
#pragma unroll
            for (int nt = 0; nt < NT; ++nt) {
                uint4 bf = sfrag[(s * NT + nt) * 32 + l];
                mma_bf16(acc[nt], ah0, ah1, ah2, ah3, bf.x, bf.y);
                mma_bf16(acc[nt], ah0, ah1, ah2, ah3, bf.z, bf.w);
                mma_bf16(acc[nt], al0, al1, al2, al3, bf.x, bf.y);
            }
            if (s < 7) { f0 = n0; f1 = n1; f2 = n2; f3 = n3; }
        }
    }

    // ---- splice: Z1 = relu(acc + b1), split to hi/lo bf16 in registers ----
    // zh[2*nt] = rows r0 pair, zh[2*nt+1] = rows r1 pair (bf16x2 each)
    uint32_t zh[2 * NT], zl[2 * NT];
#pragma unroll
    for (int nt = 0; nt < NT; ++nt) {
        int c0 = nt * 8 + 2 * t;
        float b0v = sbias1[c0], b1v = sbias1[c0 + 1];
        float v0 = fmaxf(acc[nt][0] + b0v, 0.f);
        float v1 = fmaxf(acc[nt][1] + b1v, 0.f);
        float v2 = fmaxf(acc[nt][2] + b0v, 0.f);
        float v3 = fmaxf(acc[nt][3] + b1v, 0.f);
        split2(make_float2(v0, v1), zh[2 * nt],     zl[2 * nt]);
        split2(make_float2(v2, v3), zh[2 * nt + 1], zl[2 * nt + 1]);
    }

    // ---- GEMM2: acc2 = Z1 @ W2 (A fragments straight from zh/zl) ----
    float acc2[NT][4];
#pragma unroll
    for (int nt = 0; nt < NT; ++nt) {
        acc2[nt][0] = 0.f; acc2[nt][1] = 0.f; acc2[nt][2] = 0.f; acc2[nt][3] = 0.f;
    }
#pragma unroll
    for (int s = 0; s < 8; ++s) {
        uint32_t ah0 = zh[4 * s],     ah1 = zh[4 * s + 1];
        uint32_t ah2 = zh[4 * s + 2], ah3 = zh[4 * s + 3];
        uint32_t al0 = zl[4 * s],     al1 = zl[4 * s + 1];
        uint32_t al2 = zl[4 * s + 2], al3 = zl[4 * s + 3];
#pragma unroll
        for (int nt = 0; nt < NT; ++nt) {
            uint4 bf = sfrag[4096 + (s * NT + nt) * 32 + l];
            mma_bf16(acc2[nt], ah0, ah1, ah2, ah3, bf.x, bf.y);
            mma_bf16(acc2[nt], ah0, ah1, ah2, ah3, bf.z, bf.w);
            mma_bf16(acc2[nt], al0, al1, al2, al3, bf.x, bf.y);
        }
    }

    const bool ok0 = row0 < M, ok1 = row1 < M;

    // ---- epilogue: bias2 + relu + store + BN stats ----
    float m0f = ok0 ? 1.f : 0.f, m1f = ok1 ? 1.f : 0.f;
#pragma unroll
    for (int nt = 0; nt < NT; ++nt) {
        int c0 = nt * 8 + 2 * t;
        float b0v = sbias2[c0], b1v = sbias2[c0 + 1];
        float v0 = fmaxf(acc2[nt][0] + b0v, 0.f);
        float v1 = fmaxf(acc2[nt][1] + b1v, 0.f);
        float v2 = fmaxf(acc2[nt][2] + b0v, 0.f);
        float v3 = fmaxf(acc2[nt][3] + b1v, 0.f);
        if (ok0) *(float2*)&out[(size_t)row0 * 128 + c0] = make_float2(v0, v1);
        if (ok1) *(float2*)&out[(size_t)row1 * 128 + c0] = make_float2(v2, v3);

        float ps0 = m0f * v0 + m1f * v2;
        float pq0 = m0f * v0 * v0 + m1f * v2 * v2;
        float ps1 = m0f * v1 + m1f * v3;
        float pq1 = m0f * v1 * v1 + m1f * v3 * v3;
#pragma unroll
        for (int m = 4; m < 32; m <<= 1) {
            ps0 += __shfl_xor_sync(0xFFFFFFFFu, ps0, m);
            pq0 += __shfl_xor_sync(0xFFFFFFFFu, pq0, m);
            ps1 += __shfl_xor_sync(0xFFFFFFFFu, ps1, m);
            pq1 += __shfl_xor_sync(0xFFFFFFFFu, pq1, m);
        }
        if (l < 4) {
            sred[0][w][c0]     = ps0;
            sred[0][w][c0 + 1] = ps1;
            sred[1][w][c0]     = pq0;
            sred[1][w][c0 + 1] = pq1;
        }
    }
    __syncthreads();
    if (tid < 128) {
        float s = 0.f, q = 0.f;
#pragma unroll
        for (int ww = 0; ww < 8; ++ww) {
            s += sred[0][ww][tid];
            q += sred[1][ww][tid];
        }
        atomicAdd(&bnacc[tid], s);
        atomicAdd(&bnacc[128 + tid], q);
    }
}

// ---------------- init / scaler --------------------------------------------
__global__ void k_zero() {
    int i = blockIdx.x * blockDim.x + threadIdx.x;
    int stride = gridDim.x * blockDim.x;
    for (int j = i; j < N_NODES; j += stride) g_deg[j] = 0;
    if (i < 2 * D) g_xacc[i] = 0.f;
    for (int j = i; j < N_LAYERS * 2 * D; j += stride) g_bnacc[j] = 0.f;
    for (int j = i; j < N_GRAPHS * D; j += stride) g_pool[j] = 0.f;
}

__global__ void k_xstats(const float* __restrict__ x) {
    int f = threadIdx.x;
    int r0 = blockIdx.x * 400;
    int r1 = min(r0 + 400, N_NODES);
    float s = 0.f, ss = 0.f;
    for (int r = r0; r < r1; ++r) {
        float v = x[(size_t)r * D + f];
        s += v; ss += v * v;
    }
    atomicAdd(&g_xacc[f], s);
    atomicAdd(&g_xacc[D + f], ss);
}

__global__ void k_xfin() {
    int f = threadIdx.x;
    float inv_n = 1.f / (float)N_NODES;
    float mu = g_xacc[f] * inv_n;
    float var = g_xacc[D + f] * inv_n - mu * mu;
    float rinv = rsqrtf(var);
    g_sc0[f] = rinv;
    g_sh0[f] = -mu * rinv;
}

// ---------------- CSR build (by dst) ----------------------------------------
__global__ void k_count(const int* __restrict__ ei) {
    int i = blockIdx.x * blockDim.x + threadIdx.x;
    int stride = gridDim.x * blockDim.x;
    for (int e = i; e < N_EDGES; e += stride)
        atomicAdd(&g_deg[ei[N_EDGES + e]], 1);
}

__global__ void k_scan1() {
    __shared__ int s[256];
    int t = threadIdx.x;
    int idx = blockIdx.x * 256 + t;
    s[t] = (idx < N_NODES) ? g_deg[idx] : 0;
    __syncthreads();
    for (int o = 128; o > 0; o >>= 1) {
        if (t < o) s[t] += s[t + o];
        __syncthreads();
    }
    if (t == 0) g_bsum[blockIdx.x] = s[0];
}

__global__ void k_scan2() {
    if (threadIdx.x == 0) {
        int run = 0;
        for (int i = 0; i < SCAN_B; ++i) {
            int v = g_bsum[i];
            g_bsumx[i] = run;
            run += v;
        }
        g_rowptr[N_NODES] = run;
    }
}

__global__ void k_scan3() {
    __shared__ int s[256];
    int t = threadIdx.x;
    int idx = blockIdx.x * 256 + t;
    int v = (idx < N_NODES) ? g_deg[idx] : 0;
    s[t] = v;
    __syncthreads();
    for (int off = 1; off < 256; off <<= 1) {
        int add = (t >= off) ? s[t - off] : 0;
        __syncthreads();
        s[t] += add;
        __syncthreads();
    }
    int excl = g_bsumx[blockIdx.x] + s[t] - v;
    if (idx < N_NODES) {
        g_rowptr[idx] = excl;
        g_cursor[idx] = excl;
    }
}

__global__ void k_fill(const int* __restrict__ ei) {
    int i = blockIdx.x * blockDim.x + threadIdx.x;
    int stride = gridDim.x * blockDim.x;
    for (int e = i; e < N_EDGES; e += stride) {
        int d = ei[N_EDGES + e];
        int p = atomicAdd(&g_cursor[d], 1);
        g_eidx[p] = ei[e];
    }
}

// ---------------- GIN aggregate with fused per-edge affine -------------------
// MODE 0: affine from precomputed arrays (standardization), no relu.
// MODE 1: BN(scale/shift) from stats + gamma/beta, with relu.
template <int MODE>
__global__ void __launch_bounds__(256) k_aggbn(
    const float* __restrict__ src, float* __restrict__ dst,
    const float* __restrict__ eps_p, int l,
    const float* __restrict__ scsrc, const float* __restrict__ shsrc,
    const float* __restrict__ bnacc,
    const float* __restrict__ gamma, const float* __restrict__ beta) {
    __shared__ float4 ssc[32], ssh[32];
    if (MODE == 1) {
        if (threadIdx.x < 128) {
            int f = threadIdx.x;
            float inv_n = 1.f / (float)N_NODES;
            float m = bnacc[f] * inv_n;
            float var = bnacc[D + f] * inv_n - m * m;
            float sc = gamma[f] * rsqrtf(var + 1e-5f);
            ((float*)ssc)[f] = sc;
            ((float*)ssh)[f] = beta[f] - m * sc;
        }
        __syncthreads();
    }
    int w = (blockIdx.x * blockDim.x + threadIdx.x) >> 5;
    int lane = threadIdx.x & 31;
    if (w >= N_NODES) return;
    float ep = 1.0f + eps_p[l];
    const float4* h4 = (const float4*)src;
    float4 sc4, sh4;
    if (MODE == 1) { sc4 = ssc[lane]; sh4 = ssh[lane]; }
    else { sc4 = ((const float4*)scsrc)[lane]; sh4 = ((const float4*)shsrc)[lane]; }

#define BNV(v) do { \
        (v).x = (v).x * sc4.x + sh4.x; \
        (v).y = (v).y * sc4.y + sh4.y; \
        (v).z = (v).z * sc4.z + sh4.z; \
        (v).w = (v).w * sc4.w + sh4.w; \
        if (MODE == 1) { \
            (v).x = fmaxf((v).x, 0.f); (v).y = fmaxf((v).y, 0.f); \
            (v).z = fmaxf((v).z, 0.f); (v).w = fmaxf((v).w, 0.f); } } while (0)

    float4 a = h4[(size_t)w * 32 + lane];
    BNV(a);
    float4 acc;
    acc.x = a.x * ep; acc.y = a.y * ep; acc.z = a.z * ep; acc.w = a.w * ep;
    int s = g_rowptr[w];
    int e = g_rowptr[w + 1];
    int i = s;
    for (; i + 1 < e; i += 2) {
        int j0 = g_eidx[i];
        int j1 = g_eidx[i + 1];
        float4 v0 = h4[(size_t)j0 * 32 + lane];
        float4 v1 = h4[(size_t)j1 * 32 + lane];
        BNV(v0);
        BNV(v1);
        acc.x += v0.x + v1.x; acc.y += v0.y + v1.y;
        acc.z += v0.z + v1.z; acc.w += v0.w + v1.w;
    }
    if (i < e) {
        int j = g_eidx[i];
        float4 v = h4[(size_t)j * 32 + lane];
        BNV(v);
        acc.x += v.x; acc.y += v.y; acc.z += v.z; acc.w += v.w;
    }
    ((float4*)dst)[(size_t)w * 32 + lane] = acc;
#undef BNV
}

// ---------------- global_add_pool with fused BN+relu -------------------------
__global__ void __launch_bounds__(256) k_poolbn(
    const float* __restrict__ src, const int* __restrict__ batch,
    const float* __restrict__ bnacc,
    const float* __restrict__ gamma, const float* __restrict__ beta) {
    __shared__ float4 ssc[32], ssh[32];
    if (threadIdx.x < 128) {
        int f = threadIdx.x;
        float inv_n = 1.f / (float)N_NODES;
        float m = bnacc[f] * inv_n;
        float var = bnacc[D + f] * inv_n - m * m;
        float sc = gamma[f] * rsqrtf(var + 1e-5f);
        ((float*)ssc)[f] = sc;
        ((float*)ssh)[f] = beta[f] - m * sc;
    }
    __syncthreads();

    const int CH = 64;
    int w = (blockIdx.x * blockDim.x + threadIdx.x) >> 5;
    int lane = threadIdx.x & 31;
    int start = w * CH;
    if (start >= N_NODES) return;
    int end = min(N_NODES, start + CH);
    const float4* h4 = (const float4*)src;
    float4 sc4 = ssc[lane], sh4 = ssh[lane];
    float4 acc = make_float4(0.f, 0.f, 0.f, 0.f);
    int cur = batch[start];
    for (int n = start; n < end; ++n) {
        int bb = batch[n];
        if (bb != cur) {
            float* p = &g_pool[cur * D + lane * 4];
            atomicAdd(p + 0, acc.x); atomicAdd(p + 1, acc.y);
            atomicAdd(p + 2, acc.z); atomicAdd(p + 3, acc.w);
            acc = make_float4(0.f, 0.f, 0.f, 0.f);
            cur = bb;
        }
        float4 v = h4[(size_t)n * 32 + lane];
        acc.x += fmaxf(v.x * sc4.x + sh4.x, 0.f);
        acc.y += fmaxf(v.y * sc4.y + sh4.y, 0.f);
        acc.z += fmaxf(v.z * sc4.z + sh4.z, 0.f);
        acc.w += fmaxf(v.w * sc4.w + sh4.w, 0.f);
    }
    float* p = &g_pool[cur * D + lane * 4];
    atomicAdd(p + 0, acc.x); atomicAdd(p + 1, acc.y);
    atomicAdd(p + 2, acc.z); atomicAdd(p + 3, acc.w);
}

// ---------------- final MLP head --------------------------------------------
__global__ void k_fc1(const float* __restrict__ w, const float* __restrict__ b) {
    __shared__ float row[D];
    int bid = blockIdx.x, t = threadIdx.x;
    row[t] = g_pool[bid * D + t];
    __syncthreads();
    float acc = b[t];
    for (int k = 0; k < D; ++k) acc += row[k] * w[k * D + t];
    g_fc1o[bid * D + t] = fmaxf(acc, 0.f);
}

__global__ void k_fc2(const float* __restrict__ w, const float* __restrict__ b) {
    __shared__ float row[D];
    int bid = blockIdx.x, t = threadIdx.x;
    row[t] = g_fc1o[bid * D + t];
    row[t + 64] = g_fc1o[bid * D + t + 64];
    __syncthreads();
    float acc = b[t];
    for (int k = 0; k < D; ++k) acc += row[k] * w[k * 64 + t];
    g_fc2o[bid * 64 + t] = fmaxf(acc, 0.f);
}

__global__ void k_fc3(const float* __restrict__ w, const float* __restrict__ b,
                      float* __restrict__ out) {
    __shared__ float row[64];
    int bid = blockIdx.x, t = threadIdx.x;
    row[t] = g_fc2o[bid * 64 + t];
    row[t + 32] = g_fc2o[bid * 64 + t + 32];
    __syncthreads();
    if (t < N_CLASS) {
        float acc = b[t];
        for (int k = 0; k < 64; ++k) acc += row[k] * w[k * N_CLASS + t];
        out[bid * N_CLASS + t] = acc;
    }
}

// ---------------- launch -----------------------------------------------------
extern "C" void kernel_launch(void* const* d_in, const int* in_sizes, int n_in,
                              void* d_out, int out_size) {
    const float* x     = (const float*)d_in[0];
    const int*   ei    = (const int*)d_in[1];
    const int*   batch = (const int*)d_in[2];
    const float* W1    = (const float*)d_in[3];
    const float* b1    = (const float*)d_in[4];
    const float* W2    = (const float*)d_in[5];
    const float* b2    = (const float*)d_in[6];
    const float* gamma = (const float*)d_in[7];
    const float* beta  = (const float*)d_in[8];
    const float* eps   = (const float*)d_in[9];
    const float* fcw1  = (const float*)d_in[10];
    const float* fcb1  = (const float*)d_in[11];
    const float* fcw2  = (const float*)d_in[12];
    const float* fcb2  = (const float*)d_in[13];
    const float* fcw3  = (const float*)d_in[14];
    const float* fcb3  = (const float*)d_in[15];
    float* out = (float*)d_out;

    cudaFuncSetAttribute(k_mlp, cudaFuncAttributeMaxDynamicSharedMemorySize,
                         MLP_SMEM);

    float *pB, *pC, *pBN, *pSc0, *pSh0;
    cudaGetSymbolAddress((void**)&pB, g_b);
    cudaGetSymbolAddress((void**)&pC, g_c);
    cudaGetSymbolAddress((void**)&pBN, g_bnacc);
    cudaGetSymbolAddress((void**)&pSc0, g_sc0);
    cudaGetSymbolAddress((void**)&pSh0, g_sh0);
    uint4* pWf;
    cudaGetSymbolAddress((void**)&pWf, g_wfrag);

    const int EW_BLOCKS = (N_NODES * 32 + 255) / 256;   // 12500

    k_zero<<<SCAN_B, 256>>>();
    k_wprep<<<8, 256>>>(W1, W2);
    k_xstats<<<250, 128>>>(x);
    k_xfin<<<1, 128>>>();

    k_count<<<1024, 256>>>(ei);
    k_scan1<<<SCAN_B, 256>>>();
    k_scan2<<<1, 32>>>();
    k_scan3<<<SCAN_B, 256>>>();
    k_fill<<<1024, 256>>>(ei);

    for (int l = 0; l < N_LAYERS; ++l) {
        if (l == 0) {
            k_aggbn<0><<<EW_BLOCKS, 256>>>(x, pC, eps, l,
                                           pSc0, pSh0,
                                           nullptr, nullptr, nullptr);
        } else {
            k_aggbn<1><<<EW_BLOCKS, 256>>>(pB, pC, eps, l,
                                           nullptr, nullptr,
                                           pBN + (l - 1) * 2 * D,
                                           gamma + (l - 1) * D,
                                           beta + (l - 1) * D);
        }
        k_mlp<<<GB_GEMM, 256, MLP_SMEM>>>(pC,
                                          pWf + (2 * l) * 4096,
                                          pWf + (2 * l + 1) * 4096,
                                          b1 + l * D, b2 + l * D,
                                          pB, N_NODES, pBN + l * 2 * D);
    }

    {
        int warps = (N_NODES + 63) / 64;
        int blocks = (warps * 32 + 255) / 256;
        k_poolbn<<<blocks, 256>>>(pB, batch,
                                  pBN + (N_LAYERS - 1) * 2 * D,
                                  gamma + (N_LAYERS - 1) * D,
                                  beta + (N_LAYERS - 1) * D);
    }
    k_fc1<<<N_GRAPHS, 128>>>(fcw1, fcb1);
    k_fc2<<<N_GRAPHS, 64>>>(fcw2, fcb2);
    k_fc3<<<N_GRAPHS, 32>>>(fcw3, fcb3, out);
}

// round 16
// speedup vs baseline: 1.0964x; 1.0964x over previous
#include <cuda_runtime.h>
#include <cuda_bf16.h>
#include <cstdint>

#define N_NODES 100000
#define N_EDGES 1600000
#define D       128
#define N_LAYERS 4
#define N_GRAPHS 64
#define N_CLASS 10

// ---------------- scratch (device globals: no allocation allowed) ----------
__device__ float g_h[N_NODES * D];     // GEMM1 intermediate
__device__ float g_b[N_NODES * D];     // per-layer MLP output (pre-BN)
__device__ float g_c[N_NODES * D];     // aggregate output (GEMM1 input)
__device__ int   g_deg[N_NODES];
__device__ int   g_rowptr[N_NODES + 1];
__device__ int   g_cursor[N_NODES];
__device__ int   g_eidx[N_EDGES];
__device__ int   g_bsum[512];
__device__ int   g_bsumx[512];
__device__ float g_xacc[2 * D];
__device__ float g_bnacc[N_LAYERS * 2 * D];   // per-layer sum/sumsq
__device__ float g_sc0[D], g_sh0[D];          // standardization affine
__device__ float g_pool[N_GRAPHS * D];
__device__ float g_fc1o[N_GRAPHS * D];
__device__ float g_fc2o[N_GRAPHS * (D / 2)];
// pre-split weights in per-lane mma fragment order:
// [mat][ (kstep*16 + ntile)*32 + lane ] = {bhi0, bhi1, blo0, blo1}
__device__ uint4 g_wfrag[8 * 4096];

#define SCAN_B 391
#define GB_GEMM 782                    // ceil(100000/128), 128 rows per CTA
#define NT 16                          // n-tiles of 8 cols -> 128 cols
#define WSMEM_BYTES (4096 * 16)        // 64 KB dynamic smem for W fragments

// ---------------- mma helpers ------------------------------------------------
__device__ __forceinline__ uint32_t b2u(__nv_bfloat162 h) {
    return reinterpret_cast<uint32_t&>(h);
}
__device__ __forceinline__ void split2(float2 v, uint32_t& hi, uint32_t& lo) {
    __nv_bfloat162 h = __float22bfloat162_rn(v);
    float2 hf = __bfloat1622float2(h);
    __nv_bfloat162 l = __float22bfloat162_rn(make_float2(v.x - hf.x, v.y - hf.y));
    hi = b2u(h);
    lo = b2u(l);
}
__device__ __forceinline__ void mma_bf16(float c[4],
                                         uint32_t a0, uint32_t a1, uint32_t a2, uint32_t a3,
                                         uint32_t b0, uint32_t b1) {
    asm volatile(
        "mma.sync.aligned.m16n8k16.row.col.f32.bf16.bf16.f32 "
        "{%0,%1,%2,%3}, {%4,%5,%6,%7}, {%8,%9}, {%0,%1,%2,%3};"
        : "+f"(c[0]), "+f"(c[1]), "+f"(c[2]), "+f"(c[3])
        : "r"(a0), "r"(a1), "r"(a2), "r"(a3), "r"(b0), "r"(b1));
}

// ---------------- weight prep: transpose + split + fragment pack ------------
__global__ void k_wprep(const float* __restrict__ W1, const float* __restrict__ W2) {
    int mat = blockIdx.x;                    // 0..7 = layer*2 + which
    int layer = mat >> 1;
    const float* src = ((mat & 1) ? W2 : W1) + layer * D * D;   // src[k*D + n]
    uint4* dst = g_wfrag + mat * 4096;
    for (int i = threadIdx.x; i < 4096; i += blockDim.x) {
        int l = i & 31;
        int pair = i >> 5;                   // 0..127
        int s = pair >> 4, nt = pair & 15;   // kstep, ntile
        int g = l >> 2, t = l & 3;
        int n = nt * 8 + g;
        int k0 = s * 16 + t * 2;
        float2 w0 = make_float2(src[k0 * D + n],       src[(k0 + 1) * D + n]);
        float2 w1 = make_float2(src[(k0 + 8) * D + n], src[(k0 + 9) * D + n]);
        uint32_t h0, l0, h1, l1;
        split2(w0, h0, l0);
        split2(w1, h1, l1);
        dst[i] = make_uint4(h0, h1, l0, l1);
    }
}

// ---------------- mma.sync split-bf16 GEMM: out = relu(A @ W + bias) --------
// Optionally accumulates BatchNorm sum/sumsq into bnacc (stats=1).
__global__ void __launch_bounds__(256)
k_gemm_mma(const float* __restrict__ A, const uint4* __restrict__ Wf,
           const float* __restrict__ bias, float* __restrict__ out,
           int M, int stats, float* __restrict__ bnacc) {
    extern __shared__ uint4 sfrag[];       // 4096 uint4 = 64 KB
    __shared__ float sbias[128];
    __shared__ float sred[2][8][128];      // BN partials per warp

    const int tid = threadIdx.x;
    const int w = tid >> 5, l = tid & 31;
    const int g = l >> 2, t = l & 3;

    for (int i = tid; i < 4096; i += 256) sfrag[i] = Wf[i];
    if (tid < 128) sbias[tid] = bias[tid];
    __syncthreads();

    const int m0 = blockIdx.x * 128;
    const int row0 = m0 + w * 16 + g;
    const int row1 = row0 + 8;
    const float* p0 = A + (size_t)min(row0, M - 1) * 128 + 2 * t;
    const float* p1 = A + (size_t)min(row1, M - 1) * 128 + 2 * t;

    float acc[NT][4];
#pragma unroll
    for (int nt = 0; nt < NT; ++nt) {
        acc[nt][0] = 0.f; acc[nt][1] = 0.f; acc[nt][2] = 0.f; acc[nt][3] = 0.f;
    }

    float2 f0 = *(const float2*)p0;
    float2 f1 = *(const float2*)p1;
    float2 f2 = *(const float2*)(p0 + 8);
    float2 f3 = *(const float2*)(p1 + 8);

#pragma unroll
    for (int s = 0; s < 8; ++s) {
        float2 n0, n1, n2, n3;
        if (s < 7) {                       // prefetch next k-step's A
            n0 = *(const float2*)(p0 + (s + 1) * 16);
            n1 = *(const float2*)(p1 + (s + 1) * 16);
            n2 = *(const float2*)(p0 + (s + 1) * 16 + 8);
            n3 = *(const float2*)(p1 + (s + 1) * 16 + 8);
        }
        uint32_t ah0, al0, ah1, al1, ah2, al2, ah3, al3;
        split2(f0, ah0, al0);
        split2(f1, ah1, al1);
        split2(f2, ah2, al2);
        split2(f3, ah3, al3);
#pragma unroll
        for (int nt = 0; nt < NT; ++nt) {
            uint4 bf = sfrag[(s * NT + nt) * 32 + l];
            mma_bf16(acc[nt], ah0, ah1, ah2, ah3, bf.x, bf.y);   // Ahi*Whi
            mma_bf16(acc[nt], ah0, ah1, ah2, ah3, bf.z, bf.w);   // Ahi*Wlo
            mma_bf16(acc[nt], al0, al1, al2, al3, bf.x, bf.y);   // Alo*Whi
        }
        if (s < 7) { f0 = n0; f1 = n1; f2 = n2; f3 = n3; }
    }

    const bool ok0 = row0 < M, ok1 = row1 < M;

    // epilogue: bias + relu + store
#pragma unroll
    for (int nt = 0; nt < NT; ++nt) {
        int c0 = nt * 8 + 2 * t;
        float b0v = sbias[c0], b1v = sbias[c0 + 1];
        float v0 = fmaxf(acc[nt][0] + b0v, 0.f);
        float v1 = fmaxf(acc[nt][1] + b1v, 0.f);
        float v2 = fmaxf(acc[nt][2] + b0v, 0.f);
        float v3 = fmaxf(acc[nt][3] + b1v, 0.f);
        if (ok0) *(float2*)&out[(size_t)row0 * 128 + c0] = make_float2(v0, v1);
        if (ok1) *(float2*)&out[(size_t)row1 * 128 + c0] = make_float2(v2, v3);
    }

    if (stats) {
        float m0f = ok0 ? 1.f : 0.f, m1f = ok1 ? 1.f : 0.f;
#pragma unroll
        for (int nt = 0; nt < NT; ++nt) {
            int c0 = nt * 8 + 2 * t;
            float b0v = sbias[c0], b1v = sbias[c0 + 1];
            float v0 = fmaxf(acc[nt][0] + b0v, 0.f);
            float v1 = fmaxf(acc[nt][1] + b1v, 0.f);
            float v2 = fmaxf(acc[nt][2] + b0v, 0.f);
            float v3 = fmaxf(acc[nt][3] + b1v, 0.f);
            float ps0 = m0f * v0 + m1f * v2;
            float pq0 = m0f * v0 * v0 + m1f * v2 * v2;
            float ps1 = m0f * v1 + m1f * v3;
            float pq1 = m0f * v1 * v1 + m1f * v3 * v3;
#pragma unroll
            for (int m = 4; m < 32; m <<= 1) {          // reduce over g lanes
                ps0 += __shfl_xor_sync(0xFFFFFFFFu, ps0, m);
                pq0 += __shfl_xor_sync(0xFFFFFFFFu, pq0, m);
                ps1 += __shfl_xor_sync(0xFFFFFFFFu, ps1, m);
                pq1 += __shfl_xor_sync(0xFFFFFFFFu, pq1, m);
            }
            if (l < 4) {                                // g==0, t=l
                sred[0][w][c0]     = ps0;
                sred[0][w][c0 + 1] = ps1;
                sred[1][w][c0]     = pq0;
                sred[1][w][c0 + 1] = pq1;
            }
        }
        __syncthreads();
        if (tid < 128) {
            float s = 0.f, q = 0.f;
#pragma unroll
            for (int ww = 0; ww < 8; ++ww) {
                s += sred[0][ww][tid];
                q += sred[1][ww][tid];
            }
            atomicAdd(&bnacc[tid], s);
            atomicAdd(&bnacc[128 + tid], q);
        }
    }
}

// ---------------- init / scaler --------------------------------------------
__global__ void k_zero() {
    int i = blockIdx.x * blockDim.x + threadIdx.x;
    int stride = gridDim.x * blockDim.x;
    for (int j = i; j < N_NODES; j += stride) g_deg[j] = 0;
    if (i < 2 * D) g_xacc[i] = 0.f;
    for (int j = i; j < N_LAYERS * 2 * D; j += stride) g_bnacc[j] = 0.f;
    for (int j = i; j < N_GRAPHS * D; j += stride) g_pool[j] = 0.f;
}

__global__ void k_xstats(const float* __restrict__ x) {
    int f = threadIdx.x;
    int r0 = blockIdx.x * 400;
    int r1 = min(r0 + 400, N_NODES);
    float s = 0.f, ss = 0.f;
    for (int r = r0; r < r1; ++r) {
        float v = x[(size_t)r * D + f];
        s += v; ss += v * v;
    }
    atomicAdd(&g_xacc[f], s);
    atomicAdd(&g_xacc[D + f], ss);
}

__global__ void k_xfin() {
    int f = threadIdx.x;
    float inv_n = 1.f / (float)N_NODES;
    float mu = g_xacc[f] * inv_n;
    float var = g_xacc[D + f] * inv_n - mu * mu;
    float rinv = rsqrtf(var);
    g_sc0[f] = rinv;
    g_sh0[f] = -mu * rinv;
}

// ---------------- CSR build (by dst) ----------------------------------------
__global__ void k_count(const int* __restrict__ ei) {
    int i = blockIdx.x * blockDim.x + threadIdx.x;
    int stride = gridDim.x * blockDim.x;
    for (int e = i; e < N_EDGES; e += stride)
        atomicAdd(&g_deg[ei[N_EDGES + e]], 1);
}

__global__ void k_scan1() {
    __shared__ int s[256];
    int t = threadIdx.x;
    int idx = blockIdx.x * 256 + t;
    s[t] = (idx < N_NODES) ? g_deg[idx] : 0;
    __syncthreads();
    for (int o = 128; o > 0; o >>= 1) {
        if (t < o) s[t] += s[t + o];
        __syncthreads();
    }
    if (t == 0) g_bsum[blockIdx.x] = s[0];
}

__global__ void k_scan2() {
    if (threadIdx.x == 0) {
        int run = 0;
        for (int i = 0; i < SCAN_B; ++i) {
            int v = g_bsum[i];
            g_bsumx[i] = run;
            run += v;
        }
        g_rowptr[N_NODES] = run;
    }
}

__global__ void k_scan3() {
    __shared__ int s[256];
    int t = threadIdx.x;
    int idx = blockIdx.x * 256 + t;
    int v = (idx < N_NODES) ? g_deg[idx] : 0;
    s[t] = v;
    __syncthreads();
    for (int off = 1; off < 256; off <<= 1) {
        int add = (t >= off) ? s[t - off] : 0;
        __syncthreads();
        s[t] += add;
        __syncthreads();
    }
    int excl = g_bsumx[blockIdx.x] + s[t] - v;
    if (idx < N_NODES) {
        g_rowptr[idx] = excl;
        g_cursor[idx] = excl;
    }
}

__global__ void k_fill(const int* __restrict__ ei) {
    int i = blockIdx.x * blockDim.x + threadIdx.x;
    int stride = gridDim.x * blockDim.x;
    for (int e = i; e < N_EDGES; e += stride) {
        int d = ei[N_EDGES + e];
        int p = atomicAdd(&g_cursor[d], 1);
        g_eidx[p] = ei[e];
    }
}

// ---------------- GIN aggregate with fused per-edge affine -------------------
// MODE 0: affine from precomputed arrays (standardization), no relu.
// MODE 1: BN(scale/shift) from stats + gamma/beta, with relu.
// Gather unrolled x4 for MLP (independent row-gathers batched per iteration).
template <int MODE>
__global__ void __launch_bounds__(256) k_aggbn(
    const float* __restrict__ src, float* __restrict__ dst,
    const float* __restrict__ eps_p, int l,
    const float* __restrict__ scsrc, const float* __restrict__ shsrc,
    const float* __restrict__ bnacc,
    const float* __restrict__ gamma, const float* __restrict__ beta) {
    __shared__ float4 ssc[32], ssh[32];
    if (MODE == 1) {
        if (threadIdx.x < 128) {
            int f = threadIdx.x;
            float inv_n = 1.f / (float)N_NODES;
            float m = bnacc[f] * inv_n;
            float var = bnacc[D + f] * inv_n - m * m;
            float sc = gamma[f] * rsqrtf(var + 1e-5f);
            ((float*)ssc)[f] = sc;
            ((float*)ssh)[f] = beta[f] - m * sc;
        }
        __syncthreads();
    }
    int w = (blockIdx.x * blockDim.x + threadIdx.x) >> 5;
    int lane = threadIdx.x & 31;
    if (w >= N_NODES) return;
    float ep = 1.0f + eps_p[l];
    const float4* h4 = (const float4*)src;
    float4 sc4, sh4;
    if (MODE == 1) { sc4 = ssc[lane]; sh4 = ssh[lane]; }
    else { sc4 = ((const float4*)scsrc)[lane]; sh4 = ((const float4*)shsrc)[lane]; }

#define BNV(v) do { \
        (v).x = (v).x * sc4.x + sh4.x; \
        (v).y = (v).y * sc4.y + sh4.y; \
        (v).z = (v).z * sc4.z + sh4.z; \
        (v).w = (v).w * sc4.w + sh4.w; \
        if (MODE == 1) { \
            (v).x = fmaxf((v).x, 0.f); (v).y = fmaxf((v).y, 0.f); \
            (v).z = fmaxf((v).z, 0.f); (v).w = fmaxf((v).w, 0.f); } } while (0)

    float4 a = h4[(size_t)w * 32 + lane];
    BNV(a);
    float4 acc;
    acc.x = a.x * ep; acc.y = a.y * ep; acc.z = a.z * ep; acc.w = a.w * ep;
    int s = g_rowptr[w];
    int e = g_rowptr[w + 1];
    int i = s;
    for (; i + 3 < e; i += 4) {            // 4 independent gathers in flight
        int j0 = g_eidx[i];
        int j1 = g_eidx[i + 1];
        int j2 = g_eidx[i + 2];
        int j3 = g_eidx[i + 3];
        float4 v0 = h4[(size_t)j0 * 32 + lane];
        float4 v1 = h4[(size_t)j1 * 32 + lane];
        float4 v2 = h4[(size_t)j2 * 32 + lane];
        float4 v3 = h4[(size_t)j3 * 32 + lane];
        BNV(v0);
        BNV(v1);
        BNV(v2);
        BNV(v3);
        acc.x += (v0.x + v1.x) + (v2.x + v3.x);
        acc.y += (v0.y + v1.y) + (v2.y + v3.y);
        acc.z += (v0.z + v1.z) + (v2.z + v3.z);
        acc.w += (v0.w + v1.w) + (v2.w + v3.w);
    }
    for (; i < e; ++i) {
        int j = g_eidx[i];
        float4 v = h4[(size_t)j * 32 + lane];
        BNV(v);
        acc.x += v.x; acc.y += v.y; acc.z += v.z; acc.w += v.w;
    }
    ((float4*)dst)[(size_t)w * 32 + lane] = acc;
#undef BNV
}

// ---------------- global_add_pool with fused BN+relu -------------------------
__global__ void __launch_bounds__(256) k_poolbn(
    const float* __restrict__ src, const int* __restrict__ batch,
    const float* __restrict__ bnacc,
    const float* __restrict__ gamma, const float* __restrict__ beta) {
    __shared__ float4 ssc[32], ssh[32];
    if (threadIdx.x < 128) {
        int f = threadIdx.x;
        float inv_n = 1.f / (float)N_NODES;
        float m = bnacc[f] * inv_n;
        float var = bnacc[D + f] * inv_n - m * m;
        float sc = gamma[f] * rsqrtf(var + 1e-5f);
        ((float*)ssc)[f] = sc;
        ((float*)ssh)[f] = beta[f] - m * sc;
    }
    __syncthreads();

    const int CH = 64;
    int w = (blockIdx.x * blockDim.x + threadIdx.x) >> 5;
    int lane = threadIdx.x & 31;
    int start = w * CH;
    if (start >= N_NODES) return;
    int end = min(N_NODES, start + CH);
    const float4* h4 = (const float4*)src;
    float4 sc4 = ssc[lane], sh4 = ssh[lane];
    float4 acc = make_float4(0.f, 0.f, 0.f, 0.f);
    int cur = batch[start];
    for (int n = start; n < end; ++n) {
        int bb = batch[n];
        if (bb != cur) {
            float* p = &g_pool[cur * D + lane * 4];
            atomicAdd(p + 0, acc.x); atomicAdd(p + 1, acc.y);
            atomicAdd(p + 2, acc.z); atomicAdd(p + 3, acc.w);
            acc = make_float4(0.f, 0.f, 0.f, 0.f);
            cur = bb;
        }
        float4 v = h4[(size_t)n * 32 + lane];
        acc.x += fmaxf(v.x * sc4.x + sh4.x, 0.f);
        acc.y += fmaxf(v.y * sc4.y + sh4.y, 0.f);
        acc.z += fmaxf(v.z * sc4.z + sh4.z, 0.f);
        acc.w += fmaxf(v.w * sc4.w + sh4.w, 0.f);
    }
    float* p = &g_pool[cur * D + lane * 4];
    atomicAdd(p + 0, acc.x); atomicAdd(p + 1, acc.y);
    atomicAdd(p + 2, acc.z); atomicAdd(p + 3, acc.w);
}

// ---------------- final MLP head --------------------------------------------
__global__ void k_fc1(const float* __restrict__ w, const float* __restrict__ b) {
    __shared__ float row[D];
    int bid = blockIdx.x, t = threadIdx.x;
    row[t] = g_pool[bid * D + t];
    __syncthreads();
    float acc = b[t];
    for (int k = 0; k < D; ++k) acc += row[k] * w[k * D + t];
    g_fc1o[bid * D + t] = fmaxf(acc, 0.f);
}

__global__ void k_fc2(const float* __restrict__ w, const float* __restrict__ b) {
    __shared__ float row[D];
    int bid = blockIdx.x, t = threadIdx.x;
    row[t] = g_fc1o[bid * D + t];
    row[t + 64] = g_fc1o[bid * D + t + 64];
    __syncthreads();
    float acc = b[t];
    for (int k = 0; k < D; ++k) acc += row[k] * w[k * 64 + t];
    g_fc2o[bid * 64 + t] = fmaxf(acc, 0.f);
}

__global__ void k_fc3(const float* __restrict__ w, const float* __restrict__ b,
                      float* __restrict__ out) {
    __shared__ float row[64];
    int bid = blockIdx.x, t = threadIdx.x;
    row[t] = g_fc2o[bid * 64 + t];
    row[t + 32] = g_fc2o[bid * 64 + t + 32];
    __syncthreads();
    if (t < N_CLASS) {
        float acc = b[t];
        for (int k = 0; k < 64; ++k) acc += row[k] * w[k * N_CLASS + t];
        out[bid * N_CLASS + t] = acc;
    }
}

// ---------------- launch -----------------------------------------------------
extern "C" void kernel_launch(void* const* d_in, const int* in_sizes, int n_in,
                              void* d_out, int out_size) {
    const float* x     = (const float*)d_in[0];
    const int*   ei    = (const int*)d_in[1];
    const int*   batch = (const int*)d_in[2];
    const float* W1    = (const float*)d_in[3];
    const float* b1    = (const float*)d_in[4];
    const float* W2    = (const float*)d_in[5];
    const float* b2    = (const float*)d_in[6];
    const float* gamma = (const float*)d_in[7];
    const float* beta  = (const float*)d_in[8];
    const float* eps   = (const float*)d_in[9];
    const float* fcw1  = (const float*)d_in[10];
    const float* fcb1  = (const float*)d_in[11];
    const float* fcw2  = (const float*)d_in[12];
    const float* fcb2  = (const float*)d_in[13];
    const float* fcw3  = (const float*)d_in[14];
    const float* fcb3  = (const float*)d_in[15];
    float* out = (float*)d_out;

    cudaFuncSetAttribute(k_gemm_mma, cudaFuncAttributeMaxDynamicSharedMemorySize,
                         WSMEM_BYTES);

    float *pH, *pB, *pC, *pBN, *pSc0, *pSh0;
    cudaGetSymbolAddress((void**)&pH, g_h);
    cudaGetSymbolAddress((void**)&pB, g_b);
    cudaGetSymbolAddress((void**)&pC, g_c);
    cudaGetSymbolAddress((void**)&pBN, g_bnacc);
    cudaGetSymbolAddress((void**)&pSc0, g_sc0);
    cudaGetSymbolAddress((void**)&pSh0, g_sh0);
    uint4* pWf;
    cudaGetSymbolAddress((void**)&pWf, g_wfrag);

    const int EW_BLOCKS = (N_NODES * 32 + 255) / 256;   // 12500

    k_zero<<<SCAN_B, 256>>>();
    k_wprep<<<8, 256>>>(W1, W2);
    k_xstats<<<250, 128>>>(x);
    k_xfin<<<1, 128>>>();

    k_count<<<1024, 256>>>(ei);
    k_scan1<<<SCAN_B, 256>>>();
    k_scan2<<<1, 32>>>();
    k_scan3<<<SCAN_B, 256>>>();
    k_fill<<<1024, 256>>>(ei);

    for (int l = 0; l < N_LAYERS; ++l) {
        if (l == 0) {
            k_aggbn<0><<<EW_BLOCKS, 256>>>(x, pC, eps, l,
                                           pSc0, pSh0,
                                           nullptr, nullptr, nullptr);
        } else {
            k_aggbn<1><<<EW_BLOCKS, 256>>>(pB, pC, eps, l,
                                           nullptr, nullptr,
                                           pBN + (l - 1) * 2 * D,
                                           gamma + (l - 1) * D,
                                           beta + (l - 1) * D);
        }
        k_gemm_mma<<<GB_GEMM, 256, WSMEM_BYTES>>>(pC, pWf + (2 * l) * 4096,
                                                  b1 + l * D, pH, N_NODES,
                                                  0, nullptr);
        k_gemm_mma<<<GB_GEMM, 256, WSMEM_BYTES>>>(pH, pWf + (2 * l + 1) * 4096,
                                                  b2 + l * D, pB, N_NODES,
                                                  1, pBN + l * 2 * D);
    }

    {
        int warps = (N_NODES + 63) / 64;
        int blocks = (warps * 32 + 255) / 256;
        k_poolbn<<<blocks, 256>>>(pB, batch,
                                  pBN + (N_LAYERS - 1) * 2 * D,
                                  gamma + (N_LAYERS - 1) * D,
                                  beta + (N_LAYERS - 1) * D);
    }
    k_fc1<<<N_GRAPHS, 128>>>(fcw1, fcb1);
    k_fc2<<<N_GRAPHS, 64>>>(fcw2, fcb2);
    k_fc3<<<N_GRAPHS, 32>>>(fcw3, fcb3, out);
}

// round 17
// speedup vs baseline: 1.1219x; 1.0233x over previous
#include <cuda_runtime.h>
#include <cuda_bf16.h>
#include <cuda_fp16.h>
#include <cstdint>

#define N_NODES 100000
#define N_EDGES 1600000
#define D       128
#define N_LAYERS 4
#define N_GRAPHS 64
#define N_CLASS 10

// ---------------- scratch (device globals: no allocation allowed) ----------
__device__ float g_h[N_NODES * D];     // GEMM1 intermediate (fp32)
__device__ uint2 g_bh[N_NODES * 32];   // per-layer MLP output, pre-BN, fp16 (4 halves/uint2)
__device__ float g_c[N_NODES * D];     // aggregate output (GEMM1 input, fp32)
__device__ int   g_deg[N_NODES];
__device__ int   g_rowptr[N_NODES + 1];
__device__ int   g_cursor[N_NODES];
__device__ int   g_eidx[N_EDGES];
__device__ int   g_bsum[512];
__device__ int   g_bsumx[512];
__device__ float g_xacc[2 * D];
__device__ float g_bnacc[N_LAYERS * 2 * D];   // per-layer sum/sumsq
__device__ float g_sc0[D], g_sh0[D];          // standardization affine
__device__ float g_pool[N_GRAPHS * D];
__device__ float g_fc1o[N_GRAPHS * D];
__device__ float g_fc2o[N_GRAPHS * (D / 2)];
// pre-split weights in per-lane mma fragment order:
// [mat][ (kstep*16 + ntile)*32 + lane ] = {bhi0, bhi1, blo0, blo1}
__device__ uint4 g_wfrag[8 * 4096];

#define SCAN_B 391
#define GB_GEMM 782                    // ceil(100000/128), 128 rows per CTA
#define NT 16                          // n-tiles of 8 cols -> 128 cols
#define WSMEM_BYTES (4096 * 16)        // 64 KB dynamic smem for W fragments

// ---------------- mma helpers ------------------------------------------------
__device__ __forceinline__ uint32_t b2u(__nv_bfloat162 h) {
    return reinterpret_cast<uint32_t&>(h);
}
__device__ __forceinline__ void split2(float2 v, uint32_t& hi, uint32_t& lo) {
    __nv_bfloat162 h = __float22bfloat162_rn(v);
    float2 hf = __bfloat1622float2(h);
    __nv_bfloat162 l = __float22bfloat162_rn(make_float2(v.x - hf.x, v.y - hf.y));
    hi = b2u(h);
    lo = b2u(l);
}
__device__ __forceinline__ void mma_bf16(float c[4],
                                         uint32_t a0, uint32_t a1, uint32_t a2, uint32_t a3,
                                         uint32_t b0, uint32_t b1) {
    asm volatile(
        "mma.sync.aligned.m16n8k16.row.col.f32.bf16.bf16.f32 "
        "{%0,%1,%2,%3}, {%4,%5,%6,%7}, {%8,%9}, {%0,%1,%2,%3};"
        : "+f"(c[0]), "+f"(c[1]), "+f"(c[2]), "+f"(c[3])
        : "r"(a0), "r"(a1), "r"(a2), "r"(a3), "r"(b0), "r"(b1));
}

// ---------------- weight prep: transpose + split + fragment pack ------------
__global__ void k_wprep(const float* __restrict__ W1, const float* __restrict__ W2) {
    int mat = blockIdx.x;                    // 0..7 = layer*2 + which
    int layer = mat >> 1;
    const float* src = ((mat & 1) ? W2 : W1) + layer * D * D;   // src[k*D + n]
    uint4* dst = g_wfrag + mat * 4096;
    for (int i = threadIdx.x; i < 4096; i += blockDim.x) {
        int l = i & 31;
        int pair = i >> 5;                   // 0..127
        int s = pair >> 4, nt = pair & 15;   // kstep, ntile
        int g = l >> 2, t = l & 3;
        int n = nt * 8 + g;
        int k0 = s * 16 + t * 2;
        float2 w0 = make_float2(src[k0 * D + n],       src[(k0 + 1) * D + n]);
        float2 w1 = make_float2(src[(k0 + 8) * D + n], src[(k0 + 9) * D + n]);
        uint32_t h0, l0, h1, l1;
        split2(w0, h0, l0);
        split2(w1, l1, l1);   // placeholder overwritten below
        split2(w1, h1, l1);
        dst[i] = make_uint4(h0, h1, l0, l1);
    }
}

// ---------------- mma.sync split-bf16 GEMM ----------------------------------
// stats=0: out = relu(A@W+bias) to fp32 `out`.
// stats=1: out = relu(A@W+bias) to fp16 `outh`, plus BN sum/sumsq into bnacc.
__global__ void __launch_bounds__(256)
k_gemm_mma(const float* __restrict__ A, const uint4* __restrict__ Wf,
           const float* __restrict__ bias, float* __restrict__ out,
           uint2* __restrict__ outh,
           int M, int stats, float* __restrict__ bnacc) {
    extern __shared__ uint4 sfrag[];       // 4096 uint4 = 64 KB
    __shared__ float sbias[128];
    __shared__ float sred[2][8][128];      // BN partials per warp

    const int tid = threadIdx.x;
    const int w = tid >> 5, l = tid & 31;
    const int g = l >> 2, t = l & 3;

    for (int i = tid; i < 4096; i += 256) sfrag[i] = Wf[i];
    if (tid < 128) sbias[tid] = bias[tid];
    __syncthreads();

    const int m0 = blockIdx.x * 128;
    const int row0 = m0 + w * 16 + g;
    const int row1 = row0 + 8;
    const float* p0 = A + (size_t)min(row0, M - 1) * 128 + 2 * t;
    const float* p1 = A + (size_t)min(row1, M - 1) * 128 + 2 * t;

    float acc[NT][4];
#pragma unroll
    for (int nt = 0; nt < NT; ++nt) {
        acc[nt][0] = 0.f; acc[nt][1] = 0.f; acc[nt][2] = 0.f; acc[nt][3] = 0.f;
    }

    float2 f0 = *(const float2*)p0;
    float2 f1 = *(const float2*)p1;
    float2 f2 = *(const float2*)(p0 + 8);
    float2 f3 = *(const float2*)(p1 + 8);

#pragma unroll
    for (int s = 0; s < 8; ++s) {
        float2 n0, n1, n2, n3;
        if (s < 7) {                       // prefetch next k-step's A
            n0 = *(const float2*)(p0 + (s + 1) * 16);
            n1 = *(const float2*)(p1 + (s + 1) * 16);
            n2 = *(const float2*)(p0 + (s + 1) * 16 + 8);
            n3 = *(const float2*)(p1 + (s + 1) * 16 + 8);
        }
        uint32_t ah0, al0, ah1, al1, ah2, al2, ah3, al3;
        split2(f0, ah0, al0);
        split2(f1, ah1, al1);
        split2(f2, ah2, al2);
        split2(f3, ah3, al3);
#pragma unroll
        for (int nt = 0; nt < NT; ++nt) {
            uint4 bf = sfrag[(s * NT + nt) * 32 + l];
            mma_bf16(acc[nt], ah0, ah1, ah2, ah3, bf.x, bf.y);   // Ahi*Whi
            mma_bf16(acc[nt], ah0, ah1, ah2, ah3, bf.z, bf.w);   // Ahi*Wlo
            mma_bf16(acc[nt], al0, al1, al2, al3, bf.x, bf.y);   // Alo*Whi
        }
        if (s < 7) { f0 = n0; f1 = n1; f2 = n2; f3 = n3; }
    }

    const bool ok0 = row0 < M, ok1 = row1 < M;
    float m0f = ok0 ? 1.f : 0.f, m1f = ok1 ? 1.f : 0.f;

    // epilogue: bias + relu + store (+ BN stats when stats=1)
    __half2* oh = (__half2*)outh;
#pragma unroll
    for (int nt = 0; nt < NT; ++nt) {
        int c0 = nt * 8 + 2 * t;
        float b0v = sbias[c0], b1v = sbias[c0 + 1];
        float v0 = fmaxf(acc[nt][0] + b0v, 0.f);
        float v1 = fmaxf(acc[nt][1] + b1v, 0.f);
        float v2 = fmaxf(acc[nt][2] + b0v, 0.f);
        float v3 = fmaxf(acc[nt][3] + b1v, 0.f);
        if (stats) {
            if (ok0) oh[(size_t)row0 * 64 + (c0 >> 1)] = __floats2half2_rn(v0, v1);
            if (ok1) oh[(size_t)row1 * 64 + (c0 >> 1)] = __floats2half2_rn(v2, v3);
            float ps0 = m0f * v0 + m1f * v2;
            float pq0 = m0f * v0 * v0 + m1f * v2 * v2;
            float ps1 = m0f * v1 + m1f * v3;
            float pq1 = m0f * v1 * v1 + m1f * v3 * v3;
#pragma unroll
            for (int m = 4; m < 32; m <<= 1) {          // reduce over g lanes
                ps0 += __shfl_xor_sync(0xFFFFFFFFu, ps0, m);
                pq0 += __shfl_xor_sync(0xFFFFFFFFu, pq0, m);
                ps1 += __shfl_xor_sync(0xFFFFFFFFu, ps1, m);
                pq1 += __shfl_xor_sync(0xFFFFFFFFu, pq1, m);
            }
            if (l < 4) {                                // g==0, t=l
                sred[0][w][c0]     = ps0;
                sred[0][w][c0 + 1] = ps1;
                sred[1][w][c0]     = pq0;
                sred[1][w][c0 + 1] = pq1;
            }
        } else {
            if (ok0) *(float2*)&out[(size_t)row0 * 128 + c0] = make_float2(v0, v1);
            if (ok1) *(float2*)&out[(size_t)row1 * 128 + c0] = make_float2(v2, v3);
        }
    }

    if (stats) {
        __syncthreads();
        if (tid < 128) {
            float s = 0.f, q = 0.f;
#pragma unroll
            for (int ww = 0; ww < 8; ++ww) {
                s += sred[0][ww][tid];
                q += sred[1][ww][tid];
            }
            atomicAdd(&bnacc[tid], s);
            atomicAdd(&bnacc[128 + tid], q);
        }
    }
}

// ---------------- init / scaler --------------------------------------------
__global__ void k_zero() {
    int i = blockIdx.x * blockDim.x + threadIdx.x;
    int stride = gridDim.x * blockDim.x;
    for (int j = i; j < N_NODES; j += stride) g_deg[j] = 0;
    if (i < 2 * D) g_xacc[i] = 0.f;
    for (int j = i; j < N_LAYERS * 2 * D; j += stride) g_bnacc[j] = 0.f;
    for (int j = i; j < N_GRAPHS * D; j += stride) g_pool[j] = 0.f;
}

__global__ void k_xstats(const float* __restrict__ x) {
    int f = threadIdx.x;
    int r0 = blockIdx.x * 400;
    int r1 = min(r0 + 400, N_NODES);
    float s = 0.f, ss = 0.f;
    for (int r = r0; r < r1; ++r) {
        float v = x[(size_t)r * D + f];
        s += v; ss += v * v;
    }
    atomicAdd(&g_xacc[f], s);
    atomicAdd(&g_xacc[D + f], ss);
}

__global__ void k_xfin() {
    int f = threadIdx.x;
    float inv_n = 1.f / (float)N_NODES;
    float mu = g_xacc[f] * inv_n;
    float var = g_xacc[D + f] * inv_n - mu * mu;
    float rinv = rsqrtf(var);
    g_sc0[f] = rinv;
    g_sh0[f] = -mu * rinv;
}

// ---------------- CSR build (by dst) ----------------------------------------
__global__ void k_count(const int* __restrict__ ei) {
    int i = blockIdx.x * blockDim.x + threadIdx.x;
    int stride = gridDim.x * blockDim.x;
    for (int e = i; e < N_EDGES; e += stride)
        atomicAdd(&g_deg[ei[N_EDGES + e]], 1);
}

__global__ void k_scan1() {
    __shared__ int s[256];
    int t = threadIdx.x;
    int idx = blockIdx.x * 256 + t;
    s[t] = (idx < N_NODES) ? g_deg[idx] : 0;
    __syncthreads();
    for (int o = 128; o > 0; o >>= 1) {
        if (t < o) s[t] += s[t + o];
        __syncthreads();
    }
    if (t == 0) g_bsum[blockIdx.x] = s[0];
}

__global__ void k_scan2() {
    if (threadIdx.x == 0) {
        int run = 0;
        for (int i = 0; i < SCAN_B; ++i) {
            int v = g_bsum[i];
            g_bsumx[i] = run;
            run += v;
        }
        g_rowptr[N_NODES] = run;
    }
}

__global__ void k_scan3() {
    __shared__ int s[256];
    int t = threadIdx.x;
    int idx = blockIdx.x * 256 + t;
    int v = (idx < N_NODES) ? g_deg[idx] : 0;
    s[t] = v;
    __syncthreads();
    for (int off = 1; off < 256; off <<= 1) {
        int add = (t >= off) ? s[t - off] : 0;
        __syncthreads();
        s[t] += add;
        __syncthreads();
    }
    int excl = g_bsumx[blockIdx.x] + s[t] - v;
    if (idx < N_NODES) {
        g_rowptr[idx] = excl;
        g_cursor[idx] = excl;
    }
}

__global__ void k_fill(const int* __restrict__ ei) {
    int i = blockIdx.x * blockDim.x + threadIdx.x;
    int stride = gridDim.x * blockDim.x;
    for (int e = i; e < N_EDGES; e += stride) {
        int d = ei[N_EDGES + e];
        int p = atomicAdd(&g_cursor[d], 1);
        g_eidx[p] = ei[e];
    }
}

// ---------------- GIN aggregate with fused per-edge affine -------------------
// MODE 0: fp32 src, affine from precomputed arrays (standardization), no relu.
// MODE 1: fp16 src (uint2 = 4 halves/lane), BN from stats + gamma/beta, relu.
template <int MODE>
__global__ void __launch_bounds__(256) k_aggbn(
    const void* __restrict__ srcv, float* __restrict__ dst,
    const float* __restrict__ eps_p, int l,
    const float* __restrict__ scsrc, const float* __restrict__ shsrc,
    const float* __restrict__ bnacc,
    const float* __restrict__ gamma, const float* __restrict__ beta) {
    __shared__ float4 ssc[32], ssh[32];
    if (MODE == 1) {
        if (threadIdx.x < 128) {
            int f = threadIdx.x;
            float inv_n = 1.f / (float)N_NODES;
            float m = bnacc[f] * inv_n;
            float var = bnacc[D + f] * inv_n - m * m;
            float sc = gamma[f] * rsqrtf(var + 1e-5f);
            ((float*)ssc)[f] = sc;
            ((float*)ssh)[f] = beta[f] - m * sc;
        }
        __syncthreads();
    }
    int w = (blockIdx.x * blockDim.x + threadIdx.x) >> 5;
    int lane = threadIdx.x & 31;
    if (w >= N_NODES) return;
    float ep = 1.0f + eps_p[l];
    const float4* h4 = (const float4*)srcv;
    const uint2* h2 = (const uint2*)srcv;
    float4 sc4, sh4;
    if (MODE == 1) { sc4 = ssc[lane]; sh4 = ssh[lane]; }
    else { sc4 = ((const float4*)scsrc)[lane]; sh4 = ((const float4*)shsrc)[lane]; }

#define LDROW(v, j) do { \
        if (MODE == 0) { \
            (v) = h4[(size_t)(j) * 32 + lane]; \
        } else { \
            uint2 r_ = h2[(size_t)(j) * 32 + lane]; \
            float2 lo_ = __half22float2(*(__half2*)&r_.x); \
            float2 hi_ = __half22float2(*(__half2*)&r_.y); \
            (v) = make_float4(lo_.x, lo_.y, hi_.x, hi_.y); \
        } } while (0)

#define BNV(v) do { \
        (v).x = (v).x * sc4.x + sh4.x; \
        (v).y = (v).y * sc4.y + sh4.y; \
        (v).z = (v).z * sc4.z + sh4.z; \
        (v).w = (v).w * sc4.w + sh4.w; \
        if (MODE == 1) { \
            (v).x = fmaxf((v).x, 0.f); (v).y = fmaxf((v).y, 0.f); \
            (v).z = fmaxf((v).z, 0.f); (v).w = fmaxf((v).w, 0.f); } } while (0)

    float4 a;
    LDROW(a, w);
    BNV(a);
    float4 acc;
    acc.x = a.x * ep; acc.y = a.y * ep; acc.z = a.z * ep; acc.w = a.w * ep;
    int s = g_rowptr[w];
    int e = g_rowptr[w + 1];
    int i = s;
    for (; i + 3 < e; i += 4) {            // 4 independent gathers in flight
        int j0 = g_eidx[i];
        int j1 = g_eidx[i + 1];
        int j2 = g_eidx[i + 2];
        int j3 = g_eidx[i + 3];
        float4 v0, v1, v2, v3;
        LDROW(v0, j0);
        LDROW(v1, j1);
        LDROW(v2, j2);
        LDROW(v3, j3);
        BNV(v0);
        BNV(v1);
        BNV(v2);
        BNV(v3);
        acc.x += (v0.x + v1.x) + (v2.x + v3.x);
        acc.y += (v0.y + v1.y) + (v2.y + v3.y);
        acc.z += (v0.z + v1.z) + (v2.z + v3.z);
        acc.w += (v0.w + v1.w) + (v2.w + v3.w);
    }
    for (; i < e; ++i) {
        int j = g_eidx[i];
        float4 v;
        LDROW(v, j);
        BNV(v);
        acc.x += v.x; acc.y += v.y; acc.z += v.z; acc.w += v.w;
    }
    ((float4*)dst)[(size_t)w * 32 + lane] = acc;
#undef BNV
#undef LDROW
}

// ---------------- global_add_pool with fused BN+relu (fp16 src) --------------
__global__ void __launch_bounds__(256) k_poolbn(
    const uint2* __restrict__ src, const int* __restrict__ batch,
    const float* __restrict__ bnacc,
    const float* __restrict__ gamma, const float* __restrict__ beta) {
    __shared__ float4 ssc[32], ssh[32];
    if (threadIdx.x < 128) {
        int f = threadIdx.x;
        float inv_n = 1.f / (float)N_NODES;
        float m = bnacc[f] * inv_n;
        float var = bnacc[D + f] * inv_n - m * m;
        float sc = gamma[f] * rsqrtf(var + 1e-5f);
        ((float*)ssc)[f] = sc;
        ((float*)ssh)[f] = beta[f] - m * sc;
    }
    __syncthreads();

    const int CH = 64;
    int w = (blockIdx.x * blockDim.x + threadIdx.x) >> 5;
    int lane = threadIdx.x & 31;
    int start = w * CH;
    if (start >= N_NODES) return;
    int end = min(N_NODES, start + CH);
    float4 sc4 = ssc[lane], sh4 = ssh[lane];
    float4 acc = make_float4(0.f, 0.f, 0.f, 0.f);
    int cur = batch[start];
    for (int n = start; n < end; ++n) {
        int bb = batch[n];
        if (bb != cur) {
            float* p = &g_pool[cur * D + lane * 4];
            atomicAdd(p + 0, acc.x); atomicAdd(p + 1, acc.y);
            atomicAdd(p + 2, acc.z); atomicAdd(p + 3, acc.w);
            acc = make_float4(0.f, 0.f, 0.f, 0.f);
            cur = bb;
        }
        uint2 r = src[(size_t)n * 32 + lane];
        float2 lo = __half22float2(*(__half2*)&r.x);
        float2 hi = __half22float2(*(__half2*)&r.y);
        acc.x += fmaxf(lo.x * sc4.x + sh4.x, 0.f);
        acc.y += fmaxf(lo.y * sc4.y + sh4.y, 0.f);
        acc.z += fmaxf(hi.x * sc4.z + sh4.z, 0.f);
        acc.w += fmaxf(hi.y * sc4.w + sh4.w, 0.f);
    }
    float* p = &g_pool[cur * D + lane * 4];
    atomicAdd(p + 0, acc.x); atomicAdd(p + 1, acc.y);
    atomicAdd(p + 2, acc.z); atomicAdd(p + 3, acc.w);
}

// ---------------- final MLP head --------------------------------------------
__global__ void k_fc1(const float* __restrict__ w, const float* __restrict__ b) {
    __shared__ float row[D];
    int bid = blockIdx.x, t = threadIdx.x;
    row[t] = g_pool[bid * D + t];
    __syncthreads();
    float acc = b[t];
    for (int k = 0; k < D; ++k) acc += row[k] * w[k * D + t];
    g_fc1o[bid * D + t] = fmaxf(acc, 0.f);
}

__global__ void k_fc2(const float* __restrict__ w, const float* __restrict__ b) {
    __shared__ float row[D];
    int bid = blockIdx.x, t = threadIdx.x;
    row[t] = g_fc1o[bid * D + t];
    row[t + 64] = g_fc1o[bid * D + t + 64];
    __syncthreads();
    float acc = b[t];
    for (int k = 0; k < D; ++k) acc += row[k] * w[k * 64 + t];
    g_fc2o[bid * 64 + t] = fmaxf(acc, 0.f);
}

__global__ void k_fc3(const float* __restrict__ w, const float* __restrict__ b,
                      float* __restrict__ out) {
    __shared__ float row[64];
    int bid = blockIdx.x, t = threadIdx.x;
    row[t] = g_fc2o[bid * 64 + t];
    row[t + 32] = g_fc2o[bid * 64 + t + 32];
    __syncthreads();
    if (t < N_CLASS) {
        float acc = b[t];
        for (int k = 0; k < 64; ++k) acc += row[k] * w[k * N_CLASS + t];
        out[bid * N_CLASS + t] = acc;
    }
}

// ---------------- launch -----------------------------------------------------
extern "C" void kernel_launch(void* const* d_in, const int* in_sizes, int n_in,
                              void* d_out, int out_size) {
    const float* x     = (const float*)d_in[0];
    const int*   ei    = (const int*)d_in[1];
    const int*   batch = (const int*)d_in[2];
    const float* W1    = (const float*)d_in[3];
    const float* b1    = (const float*)d_in[4];
    const float* W2    = (const float*)d_in[5];
    const float* b2    = (const float*)d_in[6];
    const float* gamma = (const float*)d_in[7];
    const float* beta  = (const float*)d_in[8];
    const float* eps   = (const float*)d_in[9];
    const float* fcw1  = (const float*)d_in[10];
    const float* fcb1  = (const float*)d_in[11];
    const float* fcw2  = (const float*)d_in[12];
    const float* fcb2  = (const float*)d_in[13];
    const float* fcw3  = (const float*)d_in[14];
    const float* fcb3  = (const float*)d_in[15];
    float* out = (float*)d_out;

    cudaFuncSetAttribute(k_gemm_mma, cudaFuncAttributeMaxDynamicSharedMemorySize,
                         WSMEM_BYTES);

    float *pH, *pC, *pBN, *pSc0, *pSh0;
    uint2 *pBH;
    cudaGetSymbolAddress((void**)&pH, g_h);
    cudaGetSymbolAddress((void**)&pBH, g_bh);
    cudaGetSymbolAddress((void**)&pC, g_c);
    cudaGetSymbolAddress((void**)&pBN, g_bnacc);
    cudaGetSymbolAddress((void**)&pSc0, g_sc0);
    cudaGetSymbolAddress((void**)&pSh0, g_sh0);
    uint4* pWf;
    cudaGetSymbolAddress((void**)&pWf, g_wfrag);

    const int EW_BLOCKS = (N_NODES * 32 + 255) / 256;   // 12500

    k_zero<<<SCAN_B, 256>>>();
    k_wprep<<<8, 256>>>(W1, W2);
    k_xstats<<<250, 128>>>(x);
    k_xfin<<<1, 128>>>();

    k_count<<<1024, 256>>>(ei);
    k_scan1<<<SCAN_B, 256>>>();
    k_scan2<<<1, 32>>>();
    k_scan3<<<SCAN_B, 256>>>();
    k_fill<<<1024, 256>>>(ei);

    for (int l = 0; l < N_LAYERS; ++l) {
        if (l == 0) {
            k_aggbn<0><<<EW_BLOCKS, 256>>>(x, pC, eps, l,
                                           pSc0, pSh0,
                                           nullptr, nullptr, nullptr);
        } else {
            k_aggbn<1><<<EW_BLOCKS, 256>>>(pBH, pC, eps, l,
                                           nullptr, nullptr,
                                           pBN + (l - 1) * 2 * D,
                                           gamma + (l - 1) * D,
                                           beta + (l - 1) * D);
        }
        k_gemm_mma<<<GB_GEMM, 256, WSMEM_BYTES>>>(pC, pWf + (2 * l) * 4096,
                                                  b1 + l * D, pH, nullptr,
                                                  N_NODES, 0, nullptr);
        k_gemm_mma<<<GB_GEMM, 256, WSMEM_BYTES>>>(pH, pWf + (2 * l + 1) * 4096,
                                                  b2 + l * D, nullptr, pBH,
                                                  N_NODES, 1, pBN + l * 2 * D);
    }

    {
        int warps = (N_NODES + 63) / 64;
        int blocks = (warps * 32 + 255) / 256;
        k_poolbn<<<blocks, 256>>>(pBH, batch,
                                  pBN + (N_LAYERS - 1) * 2 * D,
                                  gamma + (N_LAYERS - 1) * D,
                                  beta + (N_LAYERS - 1) * D);
    }
    k_fc1<<<N_GRAPHS, 128>>>(fcw1, fcb1);
    k_fc2<<<N_GRAPHS, 64>>>(fcw2, fcb2);
    k_fc3<<<N_GRAPHS, 32>>>(fcw3, fcb3, out);
}